// round 11
// baseline (speedup 1.0000x reference)
#include <cuda_runtime.h>
#include <cstdint>

#define N_NODES 16384
#define IN_DIM  512
#define OUT_DIM 256

// ---------------------------------------------------------------------------
// Device scratch (no runtime allocation allowed)
// ---------------------------------------------------------------------------
__device__ float g_dinv[N_NODES];                         // 64 KB
__device__ float g_feat[(size_t)N_NODES * OUT_DIM];       // 16 MB: g (m-major, fp32) for self-loop
__device__ float g_gT[(size_t)OUT_DIM * N_NODES];         // 16 MB: g^T (n-major, tf32-rounded) = B operand

// ---------------------------------------------------------------------------
// Helpers
// ---------------------------------------------------------------------------
__device__ __forceinline__ unsigned smem_u32(const void* p) {
    unsigned r;
    asm("{ .reg .u64 t; cvta.to.shared.u64 t, %1; cvt.u32.u64 %0, t; }"
        : "=r"(r) : "l"(p));
    return r;
}

#define CP_ASYNC16(dst, src) \
    asm volatile("cp.async.cg.shared.global [%0], [%1], 16;\n" :: "r"(dst), "l"(src))
#define CP_COMMIT() asm volatile("cp.async.commit_group;\n" ::: "memory")
#define CP_WAIT1()  asm volatile("cp.async.wait_group 1;\n" ::: "memory")

__device__ __forceinline__ unsigned tf32_rna(float x) {
    unsigned r;
    asm("cvt.rna.tf32.f32 %0, %1;" : "=r"(r) : "f"(x));
    return r;
}

__device__ __forceinline__ void mma_tf32(float& d0, float& d1, float& d2, float& d3,
                                         unsigned a0, unsigned a1, unsigned a2, unsigned a3,
                                         unsigned b0, unsigned b1) {
    asm volatile(
        "mma.sync.aligned.m16n8k8.row.col.f32.tf32.tf32.f32 "
        "{%0,%1,%2,%3}, {%4,%5,%6,%7}, {%8,%9}, {%0,%1,%2,%3};\n"
        : "+f"(d0), "+f"(d1), "+f"(d2), "+f"(d3)
        : "r"(a0), "r"(a1), "r"(a2), "r"(a3), "r"(b0), "r"(b1));
}

// ---------------------------------------------------------------------------
// Kernel 1: d_inv_sqrt[i] = rsqrt(1 + sum_j A[i,j])   (at HBM roofline)
// ---------------------------------------------------------------------------
__global__ void rowsum_kernel(const float* __restrict__ A) {
    const int row = blockIdx.x;
    const float4* a = reinterpret_cast<const float4*>(A + (size_t)row * N_NODES);
    float s = 0.f;
    for (int j = threadIdx.x; j < N_NODES / 4; j += blockDim.x) {
        float4 v = a[j];
        s += (v.x + v.y) + (v.z + v.w);
    }
    __shared__ float red[8];
    #pragma unroll
    for (int o = 16; o > 0; o >>= 1) s += __shfl_down_sync(0xffffffffu, s, o);
    if ((threadIdx.x & 31) == 0) red[threadIdx.x >> 5] = s;
    __syncthreads();
    if (threadIdx.x < 8) {
        s = red[threadIdx.x];
        #pragma unroll
        for (int o = 4; o > 0; o >>= 1) s += __shfl_down_sync(0xffu, s, o);
        if (threadIdx.x == 0) g_dinv[row] = rsqrtf(s + 1.0f);
    }
}

// ---------------------------------------------------------------------------
// Kernel 2: g[m,n] = d[m]*(x[m,:]@W[n,:] + b[n])
// Writes g_feat (m-major fp32) and g_gT (n-major, tf32-RN-rounded).
// ---------------------------------------------------------------------------
__global__ void linear_kernel(const float* __restrict__ x,
                              const float* __restrict__ W,
                              const float* __restrict__ bias) {
    const int BM = 64, BN = 64, BK = 16;
    __shared__ float Xs[BK][BM + 4];
    __shared__ float Ws[BK][BN + 4];

    const int m0 = blockIdx.y * BM;
    const int n0 = blockIdx.x * BN;
    const int tid = threadIdx.x;
    const int tx = tid & 15;
    const int ty = tid >> 4;

    float acc[4][4] = {};

    const int lr = tid >> 2;
    const int lc = (tid & 3) * 4;

    for (int kt = 0; kt < IN_DIM; kt += BK) {
        float4 v = *reinterpret_cast<const float4*>(x + (size_t)(m0 + lr) * IN_DIM + kt + lc);
        Xs[lc + 0][lr] = v.x; Xs[lc + 1][lr] = v.y;
        Xs[lc + 2][lr] = v.z; Xs[lc + 3][lr] = v.w;
        float4 w = *reinterpret_cast<const float4*>(W + (size_t)(n0 + lr) * IN_DIM + kt + lc);
        Ws[lc + 0][lr] = w.x; Ws[lc + 1][lr] = w.y;
        Ws[lc + 2][lr] = w.z; Ws[lc + 3][lr] = w.w;
        __syncthreads();

        #pragma unroll
        for (int k = 0; k < BK; k++) {
            float af[4], bf[4];
            #pragma unroll
            for (int i = 0; i < 4; i++) af[i] = Xs[k][ty * 4 + i];
            #pragma unroll
            for (int j = 0; j < 4; j++) bf[j] = Ws[k][tx * 4 + j];
            #pragma unroll
            for (int i = 0; i < 4; i++)
                #pragma unroll
                for (int j = 0; j < 4; j++)
                    acc[i][j] = fmaf(af[i], bf[j], acc[i][j]);
        }
        __syncthreads();
    }

    float dv[4];
    #pragma unroll
    for (int i = 0; i < 4; i++) dv[i] = g_dinv[m0 + ty * 4 + i];

    // m-major fp32 rows (coalesced float4 per i)
    #pragma unroll
    for (int i = 0; i < 4; i++) {
        const int gm = m0 + ty * 4 + i;
        float4 o;
        o.x = dv[i] * (acc[i][0] + bias[n0 + tx * 4 + 0]);
        o.y = dv[i] * (acc[i][1] + bias[n0 + tx * 4 + 1]);
        o.z = dv[i] * (acc[i][2] + bias[n0 + tx * 4 + 2]);
        o.w = dv[i] * (acc[i][3] + bias[n0 + tx * 4 + 3]);
        *reinterpret_cast<float4*>(g_feat + (size_t)gm * OUT_DIM + n0 + tx * 4) = o;
    }
    // n-major tf32-rounded rows (uint4 per j: 4 contiguous k = gm)
    #pragma unroll
    for (int j = 0; j < 4; j++) {
        const int gn = n0 + tx * 4 + j;
        unsigned u[4];
        #pragma unroll
        for (int i = 0; i < 4; i++)
            u[i] = tf32_rna(dv[i] * (acc[i][j] + bias[gn]));
        uint4 o = make_uint4(u[0], u[1], u[2], u[3]);
        *reinterpret_cast<uint4*>(g_gT + (size_t)gn * N_NODES + m0 + ty * 4) = o;
    }
}

// ---------------------------------------------------------------------------
// Kernel 3: out[m,:] = d[m]*( A[m,:] @ g + g[m,:] )  via mma.sync tf32 (HMMA).
// CTA tile 128(M) x 256(N full width), BK=32, 512 threads = 16 warps (4x4),
// warp tile 32x64 = 2 m-tiles x 8 n-tiles of m16n8k8. 3-stage cp.async:
// chunk c lives in stage c%3 on BOTH the read and the prefetch side.
// SMEM rows padded to 36 floats => conflict-free fragment loads.
// ---------------------------------------------------------------------------
#define NC        (N_NODES / 32)          // 512 chunks
#define RS        36                      // padded row stride (floats)
#define A_FLOATS  (128 * RS)              // 4608
#define B_FLOATS  (256 * RS)              // 9216
#define STG_FL    (A_FLOATS + B_FLOATS)   // 13824 floats = 55296 B
#define AGG_SMEM  (3 * STG_FL * 4)        // 165888 B

__global__ void __launch_bounds__(512, 1)
agg_kernel(const float* __restrict__ A, float* __restrict__ out) {
    extern __shared__ float smf[];
    const int tid  = threadIdx.x;
    const int wid  = tid >> 5;
    const int lane = tid & 31;
    const int gid  = lane >> 2;     // 0..7
    const int tig  = lane & 3;      // 0..3
    const int wm   = wid & 3;       // warp row  (M blocks of 32)
    const int wn   = wid >> 2;      // warp col  (N blocks of 64)
    const int m0   = blockIdx.x * 128;

    // ---- cp.async geometry ----
    // A tile: 128 rows x 128 B. thread t: row t>>2, 32B quarter (t&3) = 2x16B.
    const int arow = tid >> 2;
    const int aoff = (tid & 3) * 32;           // byte offset within row
    const char* agp = reinterpret_cast<const char*>(A + (size_t)(m0 + arow) * N_NODES) + aoff;
    // B tile: 256 rows x 128 B. thread t: row t>>1, 64B half (t&1) = 4x16B.
    const int brow = tid >> 1;
    const int boff = (tid & 1) * 64;
    const char* bgp = reinterpret_cast<const char*>(g_gT + (size_t)brow * N_NODES) + boff;

    unsigned sA[3], sB[3];
    #pragma unroll
    for (int s = 0; s < 3; s++) {
        float* st = smf + s * STG_FL;
        sA[s] = smem_u32(st + arow * RS) + aoff;
        sB[s] = smem_u32(st + A_FLOATS + brow * RS) + boff;
    }

    // ---- prologue: prefetch chunks 0,1 into stages 0,1 ----
    #pragma unroll
    for (int p = 0; p < 2; p++) {
        #pragma unroll
        for (int i = 0; i < 2; i++) CP_ASYNC16(sA[p] + i * 16, agp + (size_t)p * 128 + i * 16);
        #pragma unroll
        for (int i = 0; i < 4; i++) CP_ASYNC16(sB[p] + i * 16, bgp + (size_t)p * 128 + i * 16);
        CP_COMMIT();
    }

    float d[2][8][4] = {};

    // ---- fragment base pointers (per stage) ----
    const float* aFB[3];
    const float* bFB[3];
    #pragma unroll
    for (int s = 0; s < 3; s++) {
        float* st = smf + s * STG_FL;
        aFB[s] = st + (wm * 32 + gid) * RS + tig;            // + mt*16*RS, +8*RS, +4, +k*8
        bFB[s] = st + A_FLOATS + (wn * 64 + gid) * RS + tig; // + nt*8*RS, +4, +k*8
    }

    for (int c = 0; c < NC; c++) {
        CP_WAIT1();                 // chunk c resident
        __syncthreads();

        const int s = c - (c / 3) * 3;   // c % 3  (read stage)
        const float* aF = aFB[s];
        const float* bF = bFB[s];

        #pragma unroll
        for (int ks = 0; ks < 4; ks++) {
            const int ko = ks * 8;
            unsigned a[2][4];
            #pragma unroll
            for (int mt = 0; mt < 2; mt++) {
                const float* ar = aF + mt * (16 * RS) + ko;
                a[mt][0] = tf32_rna(ar[0]);
                a[mt][1] = tf32_rna(ar[8 * RS]);
                a[mt][2] = tf32_rna(ar[4]);
                a[mt][3] = tf32_rna(ar[8 * RS + 4]);
            }
            #pragma unroll
            for (int nt = 0; nt < 8; nt++) {
                const float* br = bF + nt * (8 * RS) + ko;
                const unsigned b0 = __float_as_uint(br[0]);
                const unsigned b1 = __float_as_uint(br[4]);
                #pragma unroll
                for (int mt = 0; mt < 2; mt++)
                    mma_tf32(d[mt][nt][0], d[mt][nt][1], d[mt][nt][2], d[mt][nt][3],
                             a[mt][0], a[mt][1], a[mt][2], a[mt][3], b0, b1);
            }
        }
        __syncthreads();            // all warps done reading stage s

        const int cp = c + 2;
        if (cp < NC) {
            // FIX (R8 post-mortem): chunk cp goes into stage cp%3 — the stage
            // freed by chunk c-1 — NOT into the stage just consumed (c%3).
            const int sp = cp - (cp / 3) * 3;
            #pragma unroll
            for (int i = 0; i < 2; i++)
                CP_ASYNC16(sA[sp] + i * 16, agp + (size_t)cp * 128 + i * 16);
            #pragma unroll
            for (int i = 0; i < 4; i++)
                CP_ASYNC16(sB[sp] + i * 16, bgp + (size_t)cp * 128 + i * 16);
        }
        CP_COMMIT();                // empty group in tail keeps wait_group 1 exact
    }

    // ---- epilogue: out[m,n] = d[m]*(acc + g[m,n]) ----
    #pragma unroll
    for (int mt = 0; mt < 2; mt++) {
        const int mA = m0 + wm * 32 + mt * 16 + gid;   // rows mA and mA+8
        const float dm0 = g_dinv[mA];
        const float dm1 = g_dinv[mA + 8];
        const float* gf0 = g_feat + (size_t)mA * OUT_DIM;
        const float* gf1 = gf0 + (size_t)8 * OUT_DIM;
        float* op0 = out + (size_t)mA * OUT_DIM;
        float* op1 = op0 + (size_t)8 * OUT_DIM;
        #pragma unroll
        for (int nt = 0; nt < 8; nt++) {
            const int n = wn * 64 + nt * 8 + 2 * tig;
            float2 gv0 = *reinterpret_cast<const float2*>(gf0 + n);
            float2 gv1 = *reinterpret_cast<const float2*>(gf1 + n);
            float2 o0, o1;
            o0.x = dm0 * (d[mt][nt][0] + gv0.x);
            o0.y = dm0 * (d[mt][nt][1] + gv0.y);
            o1.x = dm1 * (d[mt][nt][2] + gv1.x);
            o1.y = dm1 * (d[mt][nt][3] + gv1.y);
            *reinterpret_cast<float2*>(op0 + n) = o0;
            *reinterpret_cast<float2*>(op1 + n) = o1;
        }
    }
}

// ---------------------------------------------------------------------------
extern "C" void kernel_launch(void* const* d_in, const int* in_sizes, int n_in,
                              void* d_out, int out_size) {
    const float* x = (const float*)d_in[0];   // [16384, 512]
    const float* A = (const float*)d_in[1];   // [16384, 16384]
    const float* W = (const float*)d_in[2];   // [256, 512]
    const float* b = (const float*)d_in[3];   // [256]
    float* out = (float*)d_out;               // [16384, 256]

    cudaFuncSetAttribute(agg_kernel, cudaFuncAttributeMaxDynamicSharedMemorySize, AGG_SMEM);

    rowsum_kernel<<<N_NODES, 256>>>(A);
    linear_kernel<<<dim3(OUT_DIM / 64, N_NODES / 64), 256>>>(x, W, b);
    agg_kernel<<<N_NODES / 128, 512, AGG_SMEM>>>(A, out);
}

// round 12
// speedup vs baseline: 1.0007x; 1.0007x over previous
#include <cuda_runtime.h>
#include <cstdint>

#define N_NODES 16384
#define IN_DIM  512
#define OUT_DIM 256

// ---------------------------------------------------------------------------
// Device scratch (no runtime allocation allowed)
// ---------------------------------------------------------------------------
__device__ float g_dinv[N_NODES];                         // 64 KB
__device__ float g_feat[(size_t)N_NODES * OUT_DIM];       // 16 MB: g (m-major, fp32) for self-loop
__device__ float g_gT[(size_t)OUT_DIM * N_NODES];         // 16 MB: g^T (n-major, tf32-rounded) = B operand

// ---------------------------------------------------------------------------
// Helpers
// ---------------------------------------------------------------------------
__device__ __forceinline__ unsigned smem_u32(const void* p) {
    unsigned r;
    asm("{ .reg .u64 t; cvta.to.shared.u64 t, %1; cvt.u32.u64 %0, t; }"
        : "=r"(r) : "l"(p));
    return r;
}

#define CP_ASYNC16(dst, src) \
    asm volatile("cp.async.cg.shared.global [%0], [%1], 16;\n" :: "r"(dst), "l"(src))
#define CP_COMMIT() asm volatile("cp.async.commit_group;\n" ::: "memory")
#define CP_WAIT1()  asm volatile("cp.async.wait_group 1;\n" ::: "memory")

__device__ __forceinline__ unsigned tf32_rna(float x) {
    unsigned r;
    asm("cvt.rna.tf32.f32 %0, %1;" : "=r"(r) : "f"(x));
    return r;
}

__device__ __forceinline__ void mma_tf32(float& d0, float& d1, float& d2, float& d3,
                                         unsigned a0, unsigned a1, unsigned a2, unsigned a3,
                                         unsigned b0, unsigned b1) {
    asm volatile(
        "mma.sync.aligned.m16n8k8.row.col.f32.tf32.tf32.f32 "
        "{%0,%1,%2,%3}, {%4,%5,%6,%7}, {%8,%9}, {%0,%1,%2,%3};\n"
        : "+f"(d0), "+f"(d1), "+f"(d2), "+f"(d3)
        : "r"(a0), "r"(a1), "r"(a2), "r"(a3), "r"(b0), "r"(b1));
}

// ---------------------------------------------------------------------------
// Kernel 1: d_inv_sqrt[i] = rsqrt(1 + sum_j A[i,j])   (at HBM roofline)
// ---------------------------------------------------------------------------
__global__ void rowsum_kernel(const float* __restrict__ A) {
    const int row = blockIdx.x;
    const float4* a = reinterpret_cast<const float4*>(A + (size_t)row * N_NODES);
    float s = 0.f;
    for (int j = threadIdx.x; j < N_NODES / 4; j += blockDim.x) {
        float4 v = a[j];
        s += (v.x + v.y) + (v.z + v.w);
    }
    __shared__ float red[8];
    #pragma unroll
    for (int o = 16; o > 0; o >>= 1) s += __shfl_down_sync(0xffffffffu, s, o);
    if ((threadIdx.x & 31) == 0) red[threadIdx.x >> 5] = s;
    __syncthreads();
    if (threadIdx.x < 8) {
        s = red[threadIdx.x];
        #pragma unroll
        for (int o = 4; o > 0; o >>= 1) s += __shfl_down_sync(0xffu, s, o);
        if (threadIdx.x == 0) g_dinv[row] = rsqrtf(s + 1.0f);
    }
}

// ---------------------------------------------------------------------------
// Kernel 2: g[m,n] = d[m]*(x[m,:]@W[n,:] + b[n])
// Writes g_feat (m-major fp32) and g_gT (n-major, tf32-RN-rounded).
// ---------------------------------------------------------------------------
__global__ void linear_kernel(const float* __restrict__ x,
                              const float* __restrict__ W,
                              const float* __restrict__ bias) {
    const int BM = 64, BN = 64, BK = 16;
    __shared__ float Xs[BK][BM + 4];
    __shared__ float Ws[BK][BN + 4];

    const int m0 = blockIdx.y * BM;
    const int n0 = blockIdx.x * BN;
    const int tid = threadIdx.x;
    const int tx = tid & 15;
    const int ty = tid >> 4;

    float acc[4][4] = {};

    const int lr = tid >> 2;
    const int lc = (tid & 3) * 4;

    for (int kt = 0; kt < IN_DIM; kt += BK) {
        float4 v = *reinterpret_cast<const float4*>(x + (size_t)(m0 + lr) * IN_DIM + kt + lc);
        Xs[lc + 0][lr] = v.x; Xs[lc + 1][lr] = v.y;
        Xs[lc + 2][lr] = v.z; Xs[lc + 3][lr] = v.w;
        float4 w = *reinterpret_cast<const float4*>(W + (size_t)(n0 + lr) * IN_DIM + kt + lc);
        Ws[lc + 0][lr] = w.x; Ws[lc + 1][lr] = w.y;
        Ws[lc + 2][lr] = w.z; Ws[lc + 3][lr] = w.w;
        __syncthreads();

        #pragma unroll
        for (int k = 0; k < BK; k++) {
            float af[4], bf[4];
            #pragma unroll
            for (int i = 0; i < 4; i++) af[i] = Xs[k][ty * 4 + i];
            #pragma unroll
            for (int j = 0; j < 4; j++) bf[j] = Ws[k][tx * 4 + j];
            #pragma unroll
            for (int i = 0; i < 4; i++)
                #pragma unroll
                for (int j = 0; j < 4; j++)
                    acc[i][j] = fmaf(af[i], bf[j], acc[i][j]);
        }
        __syncthreads();
    }

    float dv[4];
    #pragma unroll
    for (int i = 0; i < 4; i++) dv[i] = g_dinv[m0 + ty * 4 + i];

    // m-major fp32 rows (coalesced float4 per i)
    #pragma unroll
    for (int i = 0; i < 4; i++) {
        const int gm = m0 + ty * 4 + i;
        float4 o;
        o.x = dv[i] * (acc[i][0] + bias[n0 + tx * 4 + 0]);
        o.y = dv[i] * (acc[i][1] + bias[n0 + tx * 4 + 1]);
        o.z = dv[i] * (acc[i][2] + bias[n0 + tx * 4 + 2]);
        o.w = dv[i] * (acc[i][3] + bias[n0 + tx * 4 + 3]);
        *reinterpret_cast<float4*>(g_feat + (size_t)gm * OUT_DIM + n0 + tx * 4) = o;
    }
    // n-major tf32-rounded rows (uint4 per j: 4 contiguous k = gm)
    #pragma unroll
    for (int j = 0; j < 4; j++) {
        const int gn = n0 + tx * 4 + j;
        unsigned u[4];
        #pragma unroll
        for (int i = 0; i < 4; i++)
            u[i] = tf32_rna(dv[i] * (acc[i][j] + bias[gn]));
        uint4 o = make_uint4(u[0], u[1], u[2], u[3]);
        *reinterpret_cast<uint4*>(g_gT + (size_t)gn * N_NODES + m0 + ty * 4) = o;
    }
}

// ---------------------------------------------------------------------------
// Kernel 3: out[m,:] = d[m]*( A[m,:] @ g + g[m,:] )  via mma.sync tf32 (HMMA).
// CTA tile 128(M) x 256(N full width), BK=32, 512 threads = 16 warps (4x4),
// warp tile 32x64 = 2 m-tiles x 8 n-tiles of m16n8k8. 3-stage cp.async:
// chunk c lives in stage c%3 on BOTH the read and the prefetch side.
// SMEM rows padded to 36 floats => conflict-free fragment loads.
// ---------------------------------------------------------------------------
#define NC        (N_NODES / 32)          // 512 chunks
#define RS        36                      // padded row stride (floats)
#define A_FLOATS  (128 * RS)              // 4608
#define B_FLOATS  (256 * RS)              // 9216
#define STG_FL    (A_FLOATS + B_FLOATS)   // 13824 floats = 55296 B
#define AGG_SMEM  (3 * STG_FL * 4)        // 165888 B

__global__ void __launch_bounds__(512, 1)
agg_kernel(const float* __restrict__ A, float* __restrict__ out) {
    extern __shared__ float smf[];
    const int tid  = threadIdx.x;
    const int wid  = tid >> 5;
    const int lane = tid & 31;
    const int gid  = lane >> 2;     // 0..7
    const int tig  = lane & 3;      // 0..3
    const int wm   = wid & 3;       // warp row  (M blocks of 32)
    const int wn   = wid >> 2;      // warp col  (N blocks of 64)
    const int m0   = blockIdx.x * 128;

    // ---- cp.async geometry ----
    // A tile: 128 rows x 128 B. thread t: row t>>2, 32B quarter (t&3) = 2x16B.
    const int arow = tid >> 2;
    const int aoff = (tid & 3) * 32;           // byte offset within row
    const char* agp = reinterpret_cast<const char*>(A + (size_t)(m0 + arow) * N_NODES) + aoff;
    // B tile: 256 rows x 128 B. thread t: row t>>1, 64B half (t&1) = 4x16B.
    const int brow = tid >> 1;
    const int boff = (tid & 1) * 64;
    const char* bgp = reinterpret_cast<const char*>(g_gT + (size_t)brow * N_NODES) + boff;

    unsigned sA[3], sB[3];
    #pragma unroll
    for (int s = 0; s < 3; s++) {
        float* st = smf + s * STG_FL;
        sA[s] = smem_u32(st + arow * RS) + aoff;
        sB[s] = smem_u32(st + A_FLOATS + brow * RS) + boff;
    }

    // ---- prologue: prefetch chunks 0,1 into stages 0,1 ----
    #pragma unroll
    for (int p = 0; p < 2; p++) {
        #pragma unroll
        for (int i = 0; i < 2; i++) CP_ASYNC16(sA[p] + i * 16, agp + (size_t)p * 128 + i * 16);
        #pragma unroll
        for (int i = 0; i < 4; i++) CP_ASYNC16(sB[p] + i * 16, bgp + (size_t)p * 128 + i * 16);
        CP_COMMIT();
    }

    float d[2][8][4] = {};

    // ---- fragment base pointers (per stage) ----
    const float* aFB[3];
    const float* bFB[3];
    #pragma unroll
    for (int s = 0; s < 3; s++) {
        float* st = smf + s * STG_FL;
        aFB[s] = st + (wm * 32 + gid) * RS + tig;            // + mt*16*RS, +8*RS, +4, +k*8
        bFB[s] = st + A_FLOATS + (wn * 64 + gid) * RS + tig; // + nt*8*RS, +4, +k*8
    }

    for (int c = 0; c < NC; c++) {
        CP_WAIT1();                 // chunk c resident
        __syncthreads();

        const int s = c - (c / 3) * 3;   // c % 3  (read stage)
        const float* aF = aFB[s];
        const float* bF = bFB[s];

        #pragma unroll
        for (int ks = 0; ks < 4; ks++) {
            const int ko = ks * 8;
            unsigned a[2][4];
            #pragma unroll
            for (int mt = 0; mt < 2; mt++) {
                const float* ar = aF + mt * (16 * RS) + ko;
                a[mt][0] = tf32_rna(ar[0]);
                a[mt][1] = tf32_rna(ar[8 * RS]);
                a[mt][2] = tf32_rna(ar[4]);
                a[mt][3] = tf32_rna(ar[8 * RS + 4]);
            }
            #pragma unroll
            for (int nt = 0; nt < 8; nt++) {
                const float* br = bF + nt * (8 * RS) + ko;
                const unsigned b0 = __float_as_uint(br[0]);
                const unsigned b1 = __float_as_uint(br[4]);
                #pragma unroll
                for (int mt = 0; mt < 2; mt++)
                    mma_tf32(d[mt][nt][0], d[mt][nt][1], d[mt][nt][2], d[mt][nt][3],
                             a[mt][0], a[mt][1], a[mt][2], a[mt][3], b0, b1);
            }
        }
        __syncthreads();            // all warps done reading stage s

        const int cp = c + 2;
        if (cp < NC) {
            // FIX (R8 post-mortem): chunk cp goes into stage cp%3 — the stage
            // freed by chunk c-1 — NOT into the stage just consumed (c%3).
            const int sp = cp - (cp / 3) * 3;
            #pragma unroll
            for (int i = 0; i < 2; i++)
                CP_ASYNC16(sA[sp] + i * 16, agp + (size_t)cp * 128 + i * 16);
            #pragma unroll
            for (int i = 0; i < 4; i++)
                CP_ASYNC16(sB[sp] + i * 16, bgp + (size_t)cp * 128 + i * 16);
        }
        CP_COMMIT();                // empty group in tail keeps wait_group 1 exact
    }

    // ---- epilogue: out[m,n] = d[m]*(acc + g[m,n]) ----
    #pragma unroll
    for (int mt = 0; mt < 2; mt++) {
        const int mA = m0 + wm * 32 + mt * 16 + gid;   // rows mA and mA+8
        const float dm0 = g_dinv[mA];
        const float dm1 = g_dinv[mA + 8];
        const float* gf0 = g_feat + (size_t)mA * OUT_DIM;
        const float* gf1 = gf0 + (size_t)8 * OUT_DIM;
        float* op0 = out + (size_t)mA * OUT_DIM;
        float* op1 = op0 + (size_t)8 * OUT_DIM;
        #pragma unroll
        for (int nt = 0; nt < 8; nt++) {
            const int n = wn * 64 + nt * 8 + 2 * tig;
            float2 gv0 = *reinterpret_cast<const float2*>(gf0 + n);
            float2 gv1 = *reinterpret_cast<const float2*>(gf1 + n);
            float2 o0, o1;
            o0.x = dm0 * (d[mt][nt][0] + gv0.x);
            o0.y = dm0 * (d[mt][nt][1] + gv0.y);
            o1.x = dm1 * (d[mt][nt][2] + gv1.x);
            o1.y = dm1 * (d[mt][nt][3] + gv1.y);
            *reinterpret_cast<float2*>(op0 + n) = o0;
            *reinterpret_cast<float2*>(op1 + n) = o1;
        }
    }
}

// ---------------------------------------------------------------------------
extern "C" void kernel_launch(void* const* d_in, const int* in_sizes, int n_in,
                              void* d_out, int out_size) {
    const float* x = (const float*)d_in[0];   // [16384, 512]
    const float* A = (const float*)d_in[1];   // [16384, 16384]
    const float* W = (const float*)d_in[2];   // [256, 512]
    const float* b = (const float*)d_in[3];   // [256]
    float* out = (float*)d_out;               // [16384, 256]

    cudaFuncSetAttribute(agg_kernel, cudaFuncAttributeMaxDynamicSharedMemorySize, AGG_SMEM);

    rowsum_kernel<<<N_NODES, 256>>>(A);
    linear_kernel<<<dim3(OUT_DIM / 64, N_NODES / 64), 256>>>(x, W, b);
    agg_kernel<<<N_NODES / 128, 512, AGG_SMEM>>>(A, out);
}

// round 13
// speedup vs baseline: 1.2827x; 1.2818x over previous
#include <cuda_runtime.h>
#include <cstdint>

#define N_NODES 16384
#define IN_DIM  512
#define OUT_DIM 256

// ---------------------------------------------------------------------------
// Device scratch (no runtime allocation allowed)
// ---------------------------------------------------------------------------
__device__ float g_dinv[N_NODES];                         // 64 KB
__device__ float g_feat[(size_t)N_NODES * OUT_DIM];       // 16 MB: g (m-major, fp32) for self-loop
__device__ float g_gT[(size_t)OUT_DIM * N_NODES];         // 16 MB: g^T (n-major, tf32-rounded) = B operand

// ---------------------------------------------------------------------------
// Helpers
// ---------------------------------------------------------------------------
__device__ __forceinline__ unsigned smem_u32(const void* p) {
    unsigned r;
    asm("{ .reg .u64 t; cvta.to.shared.u64 t, %1; cvt.u32.u64 %0, t; }"
        : "=r"(r) : "l"(p));
    return r;
}

#define CP_ASYNC16(dst, src) \
    asm volatile("cp.async.cg.shared.global [%0], [%1], 16;\n" :: "r"(dst), "l"(src))
#define CP_COMMIT() asm volatile("cp.async.commit_group;\n" ::: "memory")
#define CP_WAIT1()  asm volatile("cp.async.wait_group 1;\n" ::: "memory")

#define LDSM_X4(r0, r1, r2, r3, addr) \
    asm volatile("ldmatrix.sync.aligned.m8n8.x4.shared.b16 {%0,%1,%2,%3}, [%4];" \
                 : "=r"(r0), "=r"(r1), "=r"(r2), "=r"(r3) : "r"(addr))

__device__ __forceinline__ unsigned tf32_rna(float x) {
    unsigned r;
    asm("cvt.rna.tf32.f32 %0, %1;" : "=r"(r) : "f"(x));
    return r;
}

__device__ __forceinline__ void mma_tf32(float& d0, float& d1, float& d2, float& d3,
                                         unsigned a0, unsigned a1, unsigned a2, unsigned a3,
                                         unsigned b0, unsigned b1) {
    asm volatile(
        "mma.sync.aligned.m16n8k8.row.col.f32.tf32.tf32.f32 "
        "{%0,%1,%2,%3}, {%4,%5,%6,%7}, {%8,%9}, {%0,%1,%2,%3};\n"
        : "+f"(d0), "+f"(d1), "+f"(d2), "+f"(d3)
        : "r"(a0), "r"(a1), "r"(a2), "r"(a3), "r"(b0), "r"(b1));
}

// ---------------------------------------------------------------------------
// Kernel 1: d_inv_sqrt[i] = rsqrt(1 + sum_j A[i,j])   (at HBM roofline)
// ---------------------------------------------------------------------------
__global__ void rowsum_kernel(const float* __restrict__ A) {
    const int row = blockIdx.x;
    const float4* a = reinterpret_cast<const float4*>(A + (size_t)row * N_NODES);
    float s = 0.f;
    for (int j = threadIdx.x; j < N_NODES / 4; j += blockDim.x) {
        float4 v = a[j];
        s += (v.x + v.y) + (v.z + v.w);
    }
    __shared__ float red[8];
    #pragma unroll
    for (int o = 16; o > 0; o >>= 1) s += __shfl_down_sync(0xffffffffu, s, o);
    if ((threadIdx.x & 31) == 0) red[threadIdx.x >> 5] = s;
    __syncthreads();
    if (threadIdx.x < 8) {
        s = red[threadIdx.x];
        #pragma unroll
        for (int o = 4; o > 0; o >>= 1) s += __shfl_down_sync(0xffu, s, o);
        if (threadIdx.x == 0) g_dinv[row] = rsqrtf(s + 1.0f);
    }
}

// ---------------------------------------------------------------------------
// Kernel 2: g[m,n] = d[m]*(x[m,:]@W[n,:] + b[n])
// Writes g_feat (m-major fp32) and g_gT (n-major, tf32-RN-rounded).
// ---------------------------------------------------------------------------
__global__ void linear_kernel(const float* __restrict__ x,
                              const float* __restrict__ W,
                              const float* __restrict__ bias) {
    const int BM = 64, BN = 64, BK = 16;
    __shared__ float Xs[BK][BM + 4];
    __shared__ float Ws[BK][BN + 4];

    const int m0 = blockIdx.y * BM;
    const int n0 = blockIdx.x * BN;
    const int tid = threadIdx.x;
    const int tx = tid & 15;
    const int ty = tid >> 4;

    float acc[4][4] = {};

    const int lr = tid >> 2;
    const int lc = (tid & 3) * 4;

    for (int kt = 0; kt < IN_DIM; kt += BK) {
        float4 v = *reinterpret_cast<const float4*>(x + (size_t)(m0 + lr) * IN_DIM + kt + lc);
        Xs[lc + 0][lr] = v.x; Xs[lc + 1][lr] = v.y;
        Xs[lc + 2][lr] = v.z; Xs[lc + 3][lr] = v.w;
        float4 w = *reinterpret_cast<const float4*>(W + (size_t)(n0 + lr) * IN_DIM + kt + lc);
        Ws[lc + 0][lr] = w.x; Ws[lc + 1][lr] = w.y;
        Ws[lc + 2][lr] = w.z; Ws[lc + 3][lr] = w.w;
        __syncthreads();

        #pragma unroll
        for (int k = 0; k < BK; k++) {
            float af[4], bf[4];
            #pragma unroll
            for (int i = 0; i < 4; i++) af[i] = Xs[k][ty * 4 + i];
            #pragma unroll
            for (int j = 0; j < 4; j++) bf[j] = Ws[k][tx * 4 + j];
            #pragma unroll
            for (int i = 0; i < 4; i++)
                #pragma unroll
                for (int j = 0; j < 4; j++)
                    acc[i][j] = fmaf(af[i], bf[j], acc[i][j]);
        }
        __syncthreads();
    }

    float dv[4];
    #pragma unroll
    for (int i = 0; i < 4; i++) dv[i] = g_dinv[m0 + ty * 4 + i];

    // m-major fp32 rows (coalesced float4 per i)
    #pragma unroll
    for (int i = 0; i < 4; i++) {
        const int gm = m0 + ty * 4 + i;
        float4 o;
        o.x = dv[i] * (acc[i][0] + bias[n0 + tx * 4 + 0]);
        o.y = dv[i] * (acc[i][1] + bias[n0 + tx * 4 + 1]);
        o.z = dv[i] * (acc[i][2] + bias[n0 + tx * 4 + 2]);
        o.w = dv[i] * (acc[i][3] + bias[n0 + tx * 4 + 3]);
        *reinterpret_cast<float4*>(g_feat + (size_t)gm * OUT_DIM + n0 + tx * 4) = o;
    }
    // n-major tf32-rounded rows (uint4 per j: 4 contiguous k = gm)
    #pragma unroll
    for (int j = 0; j < 4; j++) {
        const int gn = n0 + tx * 4 + j;
        unsigned u[4];
        #pragma unroll
        for (int i = 0; i < 4; i++)
            u[i] = tf32_rna(dv[i] * (acc[i][j] + bias[gn]));
        uint4 o = make_uint4(u[0], u[1], u[2], u[3]);
        *reinterpret_cast<uint4*>(g_gT + (size_t)gn * N_NODES + m0 + ty * 4) = o;
    }
}

// ---------------------------------------------------------------------------
// Kernel 3: out[m,:] = d[m]*( A[m,:] @ g + g[m,:] )  via mma.sync tf32 (HMMA).
// CTA 128(M) x 256(N full width), BK=32, 512 threads = 16 warps (4x4),
// warp tile 32x64. Fragments loaded with ldmatrix.x4 (1 LDSM = full A frag;
// 1 LDSM = b0/b1 for two n-tiles). 3-stage cp.async ring, ONE sync per chunk,
// prefetch hoisted before the MMA phase.
// SMEM rows padded to 36 floats (144 B) => conflict-free LDSM phases.
// ---------------------------------------------------------------------------
#define NC        (N_NODES / 32)          // 512 chunks
#define RS        36                      // padded row stride (floats)
#define A_FLOATS  (128 * RS)              // 4608
#define B_FLOATS  (256 * RS)              // 9216
#define STG_FL    (A_FLOATS + B_FLOATS)   // 13824 floats
#define STG_B     (STG_FL * 4)            // 55296 B
#define AGG_SMEM  (3 * STG_B)             // 165888 B

__global__ void __launch_bounds__(512, 1)
agg_kernel(const float* __restrict__ A, float* __restrict__ out) {
    extern __shared__ float smf[];
    const int tid  = threadIdx.x;
    const int wid  = tid >> 5;
    const int lane = tid & 31;
    const int gid  = lane >> 2;     // 0..7
    const int tig  = lane & 3;      // 0..3
    const int q    = lane >> 3;     // ldmatrix quad 0..3
    const int w8   = lane & 7;      // row within quad
    const int wm   = wid & 3;       // warp row  (M blocks of 32)
    const int wn   = wid >> 2;      // warp col  (N blocks of 64)
    const int m0   = blockIdx.x * 128;

    // ---- cp.async geometry ----
    const int arow = tid >> 2;
    const int aoff = (tid & 3) * 32;
    const char* agp = reinterpret_cast<const char*>(A + (size_t)(m0 + arow) * N_NODES) + aoff;
    const int brow = tid >> 1;
    const int boff = (tid & 1) * 64;
    const char* bgp = reinterpret_cast<const char*>(g_gT + (size_t)brow * N_NODES) + boff;

    const unsigned sm0 = smem_u32(smf);
    const unsigned sA0 = sm0 + (arow * RS) * 4 + aoff;
    const unsigned sB0 = sm0 + (A_FLOATS + brow * RS) * 4 + boff;

    // ---- ldmatrix per-lane base addresses (stage 0, ks 0) ----
    // A frag (mt): matrices a0..a3 <- quads (rowblk=q&1, bytehalf=q>>1)
    unsigned aL0[2];
    #pragma unroll
    for (int mt = 0; mt < 2; mt++)
        aL0[mt] = sm0 + ((wm * 32 + mt * 16 + (q & 1) * 8 + w8) * RS) * 4 + (q >> 1) * 16;
    // B frag (j covers n-tiles 2j,2j+1): matrices b0,b1,b0',b1' <- (nrowblk=q>>1, bytehalf=q&1)
    unsigned bL0[4];
    #pragma unroll
    for (int j = 0; j < 4; j++)
        bL0[j] = sm0 + (A_FLOATS + (wn * 64 + j * 16 + (q >> 1) * 8 + w8) * RS) * 4 + (q & 1) * 16;

    // ---- prologue: prefetch chunks 0,1 into stages 0,1 ----
    #pragma unroll
    for (int p = 0; p < 2; p++) {
        #pragma unroll
        for (int i = 0; i < 2; i++) CP_ASYNC16(sA0 + p * STG_B + i * 16, agp + (size_t)p * 128 + i * 16);
        #pragma unroll
        for (int i = 0; i < 4; i++) CP_ASYNC16(sB0 + p * STG_B + i * 16, bgp + (size_t)p * 128 + i * 16);
        CP_COMMIT();
    }

    float d[2][8][4] = {};

    for (int c = 0; c < NC; c++) {
        CP_WAIT1();                      // chunk c resident
        __syncthreads();                 // also protects stage (c+2)%3 WAR (read in iter c-1)

        // ---- prefetch chunk c+2 into stage (c+2)%3 BEFORE compute ----
        const int cp = c + 2;
        if (cp < NC) {
            const int sp = cp - (cp / 3) * 3;
            #pragma unroll
            for (int i = 0; i < 2; i++)
                CP_ASYNC16(sA0 + sp * STG_B + i * 16, agp + (size_t)cp * 128 + i * 16);
            #pragma unroll
            for (int i = 0; i < 4; i++)
                CP_ASYNC16(sB0 + sp * STG_B + i * 16, bgp + (size_t)cp * 128 + i * 16);
        }
        CP_COMMIT();                     // empty group in tail keeps wait_group 1 exact

        // ---- MMA phase on stage c%3 ----
        const int s = c - (c / 3) * 3;
        const unsigned soff = (unsigned)s * STG_B;

        #pragma unroll
        for (int ks = 0; ks < 4; ks++) {
            const unsigned ko = (unsigned)ks * 32;   // bytes: 8 tf32
            unsigned a[2][4];
            #pragma unroll
            for (int mt = 0; mt < 2; mt++)
                LDSM_X4(a[mt][0], a[mt][1], a[mt][2], a[mt][3], aL0[mt] + soff + ko);
            unsigned bb[4][4];
            #pragma unroll
            for (int j = 0; j < 4; j++)
                LDSM_X4(bb[j][0], bb[j][1], bb[j][2], bb[j][3], bL0[j] + soff + ko);

            #pragma unroll
            for (int j = 0; j < 4; j++) {
                #pragma unroll
                for (int mt = 0; mt < 2; mt++) {
                    mma_tf32(d[mt][2*j][0], d[mt][2*j][1], d[mt][2*j][2], d[mt][2*j][3],
                             a[mt][0], a[mt][1], a[mt][2], a[mt][3], bb[j][0], bb[j][1]);
                    mma_tf32(d[mt][2*j+1][0], d[mt][2*j+1][1], d[mt][2*j+1][2], d[mt][2*j+1][3],
                             a[mt][0], a[mt][1], a[mt][2], a[mt][3], bb[j][2], bb[j][3]);
                }
            }
        }
    }

    // ---- epilogue: out[m,n] = d[m]*(acc + g[m,n]) ----
    #pragma unroll
    for (int mt = 0; mt < 2; mt++) {
        const int mA = m0 + wm * 32 + mt * 16 + gid;   // rows mA and mA+8
        const float dm0 = g_dinv[mA];
        const float dm1 = g_dinv[mA + 8];
        const float* gf0 = g_feat + (size_t)mA * OUT_DIM;
        const float* gf1 = gf0 + (size_t)8 * OUT_DIM;
        float* op0 = out + (size_t)mA * OUT_DIM;
        float* op1 = op0 + (size_t)8 * OUT_DIM;
        #pragma unroll
        for (int nt = 0; nt < 8; nt++) {
            const int n = wn * 64 + nt * 8 + 2 * tig;
            float2 gv0 = *reinterpret_cast<const float2*>(gf0 + n);
            float2 gv1 = *reinterpret_cast<const float2*>(gf1 + n);
            float2 o0, o1;
            o0.x = dm0 * (d[mt][nt][0] + gv0.x);
            o0.y = dm0 * (d[mt][nt][1] + gv0.y);
            o1.x = dm1 * (d[mt][nt][2] + gv1.x);
            o1.y = dm1 * (d[mt][nt][3] + gv1.y);
            *reinterpret_cast<float2*>(op0 + n) = o0;
            *reinterpret_cast<float2*>(op1 + n) = o1;
        }
    }
}

// ---------------------------------------------------------------------------
extern "C" void kernel_launch(void* const* d_in, const int* in_sizes, int n_in,
                              void* d_out, int out_size) {
    const float* x = (const float*)d_in[0];   // [16384, 512]
    const float* A = (const float*)d_in[1];   // [16384, 16384]
    const float* W = (const float*)d_in[2];   // [256, 512]
    const float* b = (const float*)d_in[3];   // [256]
    float* out = (float*)d_out;               // [16384, 256]

    cudaFuncSetAttribute(agg_kernel, cudaFuncAttributeMaxDynamicSharedMemorySize, AGG_SMEM);

    rowsum_kernel<<<N_NODES, 256>>>(A);
    linear_kernel<<<dim3(OUT_DIM / 64, N_NODES / 64), 256>>>(x, W, b);
    agg_kernel<<<N_NODES / 128, 512, AGG_SMEM>>>(A, out);
}

// round 14
// speedup vs baseline: 1.2844x; 1.0013x over previous
#include <cuda_runtime.h>
#include <cstdint>

#define N_NODES 16384
#define IN_DIM  512
#define OUT_DIM 256

// ---------------------------------------------------------------------------
// Device scratch (no runtime allocation allowed)
// ---------------------------------------------------------------------------
__device__ float g_dinv[N_NODES];                         // 64 KB
__device__ float g_feat[(size_t)N_NODES * OUT_DIM];       // 16 MB: g (m-major, fp32) for self-loop
__device__ float g_gT[(size_t)OUT_DIM * N_NODES];         // 16 MB: g^T (n-major, tf32-rounded) = B operand

// ---------------------------------------------------------------------------
// Helpers
// ---------------------------------------------------------------------------
__device__ __forceinline__ unsigned smem_u32(const void* p) {
    unsigned r;
    asm("{ .reg .u64 t; cvta.to.shared.u64 t, %1; cvt.u32.u64 %0, t; }"
        : "=r"(r) : "l"(p));
    return r;
}

#define CP_ASYNC16(dst, src) \
    asm volatile("cp.async.cg.shared.global [%0], [%1], 16;\n" :: "r"(dst), "l"(src))
#define CP_COMMIT() asm volatile("cp.async.commit_group;\n" ::: "memory")
#define CP_WAIT1()  asm volatile("cp.async.wait_group 1;\n" ::: "memory")

#define LDSM_X4(r0, r1, r2, r3, addr) \
    asm volatile("ldmatrix.sync.aligned.m8n8.x4.shared.b16 {%0,%1,%2,%3}, [%4];" \
                 : "=r"(r0), "=r"(r1), "=r"(r2), "=r"(r3) : "r"(addr))

__device__ __forceinline__ unsigned tf32_rna(float x) {
    unsigned r;
    asm("cvt.rna.tf32.f32 %0, %1;" : "=r"(r) : "f"(x));
    return r;
}

__device__ __forceinline__ void mma_tf32(float& d0, float& d1, float& d2, float& d3,
                                         unsigned a0, unsigned a1, unsigned a2, unsigned a3,
                                         unsigned b0, unsigned b1) {
    asm volatile(
        "mma.sync.aligned.m16n8k8.row.col.f32.tf32.tf32.f32 "
        "{%0,%1,%2,%3}, {%4,%5,%6,%7}, {%8,%9}, {%0,%1,%2,%3};\n"
        : "+f"(d0), "+f"(d1), "+f"(d2), "+f"(d3)
        : "r"(a0), "r"(a1), "r"(a2), "r"(a3), "r"(b0), "r"(b1));
}

// ---------------------------------------------------------------------------
// Kernel 1: d_inv_sqrt[i] = rsqrt(1 + sum_j A[i,j])   (at HBM roofline)
// ---------------------------------------------------------------------------
__global__ void rowsum_kernel(const float* __restrict__ A) {
    const int row = blockIdx.x;
    const float4* a = reinterpret_cast<const float4*>(A + (size_t)row * N_NODES);
    float s = 0.f;
    for (int j = threadIdx.x; j < N_NODES / 4; j += blockDim.x) {
        float4 v = a[j];
        s += (v.x + v.y) + (v.z + v.w);
    }
    __shared__ float red[8];
    #pragma unroll
    for (int o = 16; o > 0; o >>= 1) s += __shfl_down_sync(0xffffffffu, s, o);
    if ((threadIdx.x & 31) == 0) red[threadIdx.x >> 5] = s;
    __syncthreads();
    if (threadIdx.x < 8) {
        s = red[threadIdx.x];
        #pragma unroll
        for (int o = 4; o > 0; o >>= 1) s += __shfl_down_sync(0xffu, s, o);
        if (threadIdx.x == 0) g_dinv[row] = rsqrtf(s + 1.0f);
    }
}

// ---------------------------------------------------------------------------
// Kernel 2: g[m,n] = d[m]*(x[m,:]@W[n,:] + b[n])
// Writes g_feat (m-major fp32) and g_gT (n-major, tf32-RN-rounded).
// ---------------------------------------------------------------------------
__global__ void linear_kernel(const float* __restrict__ x,
                              const float* __restrict__ W,
                              const float* __restrict__ bias) {
    const int BM = 64, BN = 64, BK = 16;
    __shared__ float Xs[BK][BM + 4];
    __shared__ float Ws[BK][BN + 4];

    const int m0 = blockIdx.y * BM;
    const int n0 = blockIdx.x * BN;
    const int tid = threadIdx.x;
    const int tx = tid & 15;
    const int ty = tid >> 4;

    float acc[4][4] = {};

    const int lr = tid >> 2;
    const int lc = (tid & 3) * 4;

    for (int kt = 0; kt < IN_DIM; kt += BK) {
        float4 v = *reinterpret_cast<const float4*>(x + (size_t)(m0 + lr) * IN_DIM + kt + lc);
        Xs[lc + 0][lr] = v.x; Xs[lc + 1][lr] = v.y;
        Xs[lc + 2][lr] = v.z; Xs[lc + 3][lr] = v.w;
        float4 w = *reinterpret_cast<const float4*>(W + (size_t)(n0 + lr) * IN_DIM + kt + lc);
        Ws[lc + 0][lr] = w.x; Ws[lc + 1][lr] = w.y;
        Ws[lc + 2][lr] = w.z; Ws[lc + 3][lr] = w.w;
        __syncthreads();

        #pragma unroll
        for (int k = 0; k < BK; k++) {
            float af[4], bf[4];
            #pragma unroll
            for (int i = 0; i < 4; i++) af[i] = Xs[k][ty * 4 + i];
            #pragma unroll
            for (int j = 0; j < 4; j++) bf[j] = Ws[k][tx * 4 + j];
            #pragma unroll
            for (int i = 0; i < 4; i++)
                #pragma unroll
                for (int j = 0; j < 4; j++)
                    acc[i][j] = fmaf(af[i], bf[j], acc[i][j]);
        }
        __syncthreads();
    }

    float dv[4];
    #pragma unroll
    for (int i = 0; i < 4; i++) dv[i] = g_dinv[m0 + ty * 4 + i];

    // m-major fp32 rows (coalesced float4 per i)
    #pragma unroll
    for (int i = 0; i < 4; i++) {
        const int gm = m0 + ty * 4 + i;
        float4 o;
        o.x = dv[i] * (acc[i][0] + bias[n0 + tx * 4 + 0]);
        o.y = dv[i] * (acc[i][1] + bias[n0 + tx * 4 + 1]);
        o.z = dv[i] * (acc[i][2] + bias[n0 + tx * 4 + 2]);
        o.w = dv[i] * (acc[i][3] + bias[n0 + tx * 4 + 3]);
        *reinterpret_cast<float4*>(g_feat + (size_t)gm * OUT_DIM + n0 + tx * 4) = o;
    }
    // n-major tf32-rounded rows (uint4 per j: 4 contiguous k = gm)
    #pragma unroll
    for (int j = 0; j < 4; j++) {
        const int gn = n0 + tx * 4 + j;
        unsigned u[4];
        #pragma unroll
        for (int i = 0; i < 4; i++)
            u[i] = tf32_rna(dv[i] * (acc[i][j] + bias[gn]));
        uint4 o = make_uint4(u[0], u[1], u[2], u[3]);
        *reinterpret_cast<uint4*>(g_gT + (size_t)gn * N_NODES + m0 + ty * 4) = o;
    }
}

// ---------------------------------------------------------------------------
// Kernel 3: out[m,:] = d[m]*( A[m,:] @ g + g[m,:] )  via mma.sync tf32 (HMMA).
// CTA 128(M) x 256(N full width), BK=32, 512 threads = 16 warps (4x4),
// warp tile 32x64. Fragments loaded with ldmatrix.x4 (1 LDSM = full A frag;
// 1 LDSM = b0/b1 for two n-tiles). 3-stage cp.async ring, ONE sync per chunk,
// prefetch hoisted before the MMA phase.
// SMEM rows padded to 36 floats (144 B) => conflict-free LDSM phases.
// ---------------------------------------------------------------------------
#define NC        (N_NODES / 32)          // 512 chunks
#define RS        36                      // padded row stride (floats)
#define A_FLOATS  (128 * RS)              // 4608
#define B_FLOATS  (256 * RS)              // 9216
#define STG_FL    (A_FLOATS + B_FLOATS)   // 13824 floats
#define STG_B     (STG_FL * 4)            // 55296 B
#define AGG_SMEM  (3 * STG_B)             // 165888 B

__global__ void __launch_bounds__(512, 1)
agg_kernel(const float* __restrict__ A, float* __restrict__ out) {
    extern __shared__ float smf[];
    const int tid  = threadIdx.x;
    const int wid  = tid >> 5;
    const int lane = tid & 31;
    const int gid  = lane >> 2;     // 0..7
    const int tig  = lane & 3;      // 0..3
    const int q    = lane >> 3;     // ldmatrix quad 0..3
    const int w8   = lane & 7;      // row within quad
    const int wm   = wid & 3;       // warp row  (M blocks of 32)
    const int wn   = wid >> 2;      // warp col  (N blocks of 64)
    const int m0   = blockIdx.x * 128;

    // ---- cp.async geometry ----
    const int arow = tid >> 2;
    const int aoff = (tid & 3) * 32;
    const char* agp = reinterpret_cast<const char*>(A + (size_t)(m0 + arow) * N_NODES) + aoff;
    const int brow = tid >> 1;
    const int boff = (tid & 1) * 64;
    const char* bgp = reinterpret_cast<const char*>(g_gT + (size_t)brow * N_NODES) + boff;

    const unsigned sm0 = smem_u32(smf);
    const unsigned sA0 = sm0 + (arow * RS) * 4 + aoff;
    const unsigned sB0 = sm0 + (A_FLOATS + brow * RS) * 4 + boff;

    // ---- ldmatrix per-lane base addresses (stage 0, ks 0) ----
    // A frag (mt): matrices a0..a3 <- quads (rowblk=q&1, bytehalf=q>>1)
    unsigned aL0[2];
    #pragma unroll
    for (int mt = 0; mt < 2; mt++)
        aL0[mt] = sm0 + ((wm * 32 + mt * 16 + (q & 1) * 8 + w8) * RS) * 4 + (q >> 1) * 16;
    // B frag (j covers n-tiles 2j,2j+1): matrices b0,b1,b0',b1' <- (nrowblk=q>>1, bytehalf=q&1)
    unsigned bL0[4];
    #pragma unroll
    for (int j = 0; j < 4; j++)
        bL0[j] = sm0 + (A_FLOATS + (wn * 64 + j * 16 + (q >> 1) * 8 + w8) * RS) * 4 + (q & 1) * 16;

    // ---- prologue: prefetch chunks 0,1 into stages 0,1 ----
    #pragma unroll
    for (int p = 0; p < 2; p++) {
        #pragma unroll
        for (int i = 0; i < 2; i++) CP_ASYNC16(sA0 + p * STG_B + i * 16, agp + (size_t)p * 128 + i * 16);
        #pragma unroll
        for (int i = 0; i < 4; i++) CP_ASYNC16(sB0 + p * STG_B + i * 16, bgp + (size_t)p * 128 + i * 16);
        CP_COMMIT();
    }

    float d[2][8][4] = {};

    for (int c = 0; c < NC; c++) {
        CP_WAIT1();                      // chunk c resident
        __syncthreads();                 // also protects stage (c+2)%3 WAR (read in iter c-1)

        // ---- prefetch chunk c+2 into stage (c+2)%3 BEFORE compute ----
        const int cp = c + 2;
        if (cp < NC) {
            const int sp = cp - (cp / 3) * 3;
            #pragma unroll
            for (int i = 0; i < 2; i++)
                CP_ASYNC16(sA0 + sp * STG_B + i * 16, agp + (size_t)cp * 128 + i * 16);
            #pragma unroll
            for (int i = 0; i < 4; i++)
                CP_ASYNC16(sB0 + sp * STG_B + i * 16, bgp + (size_t)cp * 128 + i * 16);
        }
        CP_COMMIT();                     // empty group in tail keeps wait_group 1 exact

        // ---- MMA phase on stage c%3 ----
        const int s = c - (c / 3) * 3;
        const unsigned soff = (unsigned)s * STG_B;

        #pragma unroll
        for (int ks = 0; ks < 4; ks++) {
            const unsigned ko = (unsigned)ks * 32;   // bytes: 8 tf32
            unsigned a[2][4];
            #pragma unroll
            for (int mt = 0; mt < 2; mt++)
                LDSM_X4(a[mt][0], a[mt][1], a[mt][2], a[mt][3], aL0[mt] + soff + ko);
            unsigned bb[4][4];
            #pragma unroll
            for (int j = 0; j < 4; j++)
                LDSM_X4(bb[j][0], bb[j][1], bb[j][2], bb[j][3], bL0[j] + soff + ko);

            #pragma unroll
            for (int j = 0; j < 4; j++) {
                #pragma unroll
                for (int mt = 0; mt < 2; mt++) {
                    mma_tf32(d[mt][2*j][0], d[mt][2*j][1], d[mt][2*j][2], d[mt][2*j][3],
                             a[mt][0], a[mt][1], a[mt][2], a[mt][3], bb[j][0], bb[j][1]);
                    mma_tf32(d[mt][2*j+1][0], d[mt][2*j+1][1], d[mt][2*j+1][2], d[mt][2*j+1][3],
                             a[mt][0], a[mt][1], a[mt][2], a[mt][3], bb[j][2], bb[j][3]);
                }
            }
        }
    }

    // ---- epilogue: out[m,n] = d[m]*(acc + g[m,n]) ----
    #pragma unroll
    for (int mt = 0; mt < 2; mt++) {
        const int mA = m0 + wm * 32 + mt * 16 + gid;   // rows mA and mA+8
        const float dm0 = g_dinv[mA];
        const float dm1 = g_dinv[mA + 8];
        const float* gf0 = g_feat + (size_t)mA * OUT_DIM;
        const float* gf1 = gf0 + (size_t)8 * OUT_DIM;
        float* op0 = out + (size_t)mA * OUT_DIM;
        float* op1 = op0 + (size_t)8 * OUT_DIM;
        #pragma unroll
        for (int nt = 0; nt < 8; nt++) {
            const int n = wn * 64 + nt * 8 + 2 * tig;
            float2 gv0 = *reinterpret_cast<const float2*>(gf0 + n);
            float2 gv1 = *reinterpret_cast<const float2*>(gf1 + n);
            float2 o0, o1;
            o0.x = dm0 * (d[mt][nt][0] + gv0.x);
            o0.y = dm0 * (d[mt][nt][1] + gv0.y);
            o1.x = dm1 * (d[mt][nt][2] + gv1.x);
            o1.y = dm1 * (d[mt][nt][3] + gv1.y);
            *reinterpret_cast<float2*>(op0 + n) = o0;
            *reinterpret_cast<float2*>(op1 + n) = o1;
        }
    }
}

// ---------------------------------------------------------------------------
extern "C" void kernel_launch(void* const* d_in, const int* in_sizes, int n_in,
                              void* d_out, int out_size) {
    const float* x = (const float*)d_in[0];   // [16384, 512]
    const float* A = (const float*)d_in[1];   // [16384, 16384]
    const float* W = (const float*)d_in[2];   // [256, 512]
    const float* b = (const float*)d_in[3];   // [256]
    float* out = (float*)d_out;               // [16384, 256]

    cudaFuncSetAttribute(agg_kernel, cudaFuncAttributeMaxDynamicSharedMemorySize, AGG_SMEM);

    rowsum_kernel<<<N_NODES, 256>>>(A);
    linear_kernel<<<dim3(OUT_DIM / 64, N_NODES / 64), 256>>>(x, W, b);
    agg_kernel<<<N_NODES / 128, 512, AGG_SMEM>>>(A, out);
}

// round 15
// speedup vs baseline: 2.0169x; 1.5703x over previous
#include <cuda_runtime.h>
#include <cuda_fp16.h>
#include <cstdint>

#define N_NODES 16384
#define IN_DIM  512
#define OUT_DIM 256

// ---------------------------------------------------------------------------
// Device scratch (no runtime allocation allowed)
// ---------------------------------------------------------------------------
__device__ float  g_dinv[N_NODES];                          // 64 KB
__device__ float  g_feat[(size_t)N_NODES * OUT_DIM];        // 16 MB: g fp32 (self-loop term)
__device__ __half g_g16T[(size_t)OUT_DIM * N_NODES];        // 8 MB:  g^T fp16 (B operand)
__device__ __half g_A16[(size_t)N_NODES * N_NODES];         // 512 MB: A fp16 (MMA A operand)

// ---------------------------------------------------------------------------
// Helpers
// ---------------------------------------------------------------------------
__device__ __forceinline__ unsigned smem_u32(const void* p) {
    unsigned r;
    asm("{ .reg .u64 t; cvta.to.shared.u64 t, %1; cvt.u32.u64 %0, t; }"
        : "=r"(r) : "l"(p));
    return r;
}

#define CP_ASYNC16(dst, src) \
    asm volatile("cp.async.cg.shared.global [%0], [%1], 16;\n" :: "r"(dst), "l"(src))
#define CP_COMMIT() asm volatile("cp.async.commit_group;\n" ::: "memory")
#define CP_WAIT2()  asm volatile("cp.async.wait_group 2;\n" ::: "memory")

#define LDSM_X4(r0, r1, r2, r3, addr) \
    asm volatile("ldmatrix.sync.aligned.m8n8.x4.shared.b16 {%0,%1,%2,%3}, [%4];" \
                 : "=r"(r0), "=r"(r1), "=r"(r2), "=r"(r3) : "r"(addr))

__device__ __forceinline__ void mma_f16(float& d0, float& d1, float& d2, float& d3,
                                        unsigned a0, unsigned a1, unsigned a2, unsigned a3,
                                        unsigned b0, unsigned b1) {
    asm volatile(
        "mma.sync.aligned.m16n8k16.row.col.f32.f16.f16.f32 "
        "{%0,%1,%2,%3}, {%4,%5,%6,%7}, {%8,%9}, {%0,%1,%2,%3};\n"
        : "+f"(d0), "+f"(d1), "+f"(d2), "+f"(d3)
        : "r"(a0), "r"(a1), "r"(a2), "r"(a3), "r"(b0), "r"(b1));
}

__device__ __forceinline__ unsigned h2_bits(__half2 h) {
    return *reinterpret_cast<unsigned*>(&h);
}

// ---------------------------------------------------------------------------
// Kernel 1: d_inv_sqrt + fp16 copy of A (piggybacked on the mandatory stream)
// ---------------------------------------------------------------------------
__global__ void rowsum_kernel(const float* __restrict__ A) {
    const int row = blockIdx.x;
    const float4* a = reinterpret_cast<const float4*>(A + (size_t)row * N_NODES);
    uint2* a16 = reinterpret_cast<uint2*>(g_A16 + (size_t)row * N_NODES);
    float s = 0.f;
    for (int j = threadIdx.x; j < N_NODES / 4; j += blockDim.x) {
        float4 v = a[j];
        s += (v.x + v.y) + (v.z + v.w);
        __half2 h0 = __floats2half2_rn(v.x, v.y);   // x->lo, y->hi
        __half2 h1 = __floats2half2_rn(v.z, v.w);
        a16[j] = make_uint2(h2_bits(h0), h2_bits(h1));
    }
    __shared__ float red[8];
    #pragma unroll
    for (int o = 16; o > 0; o >>= 1) s += __shfl_down_sync(0xffffffffu, s, o);
    if ((threadIdx.x & 31) == 0) red[threadIdx.x >> 5] = s;
    __syncthreads();
    if (threadIdx.x < 8) {
        s = red[threadIdx.x];
        #pragma unroll
        for (int o = 4; o > 0; o >>= 1) s += __shfl_down_sync(0xffu, s, o);
        if (threadIdx.x == 0) g_dinv[row] = rsqrtf(s + 1.0f);
    }
}

// ---------------------------------------------------------------------------
// Kernel 2: g[m,n] = d[m]*(x[m,:]@W[n,:] + b[n])
// Writes g_feat (m-major fp32) and g_g16T (n-major fp16, RN).
// ---------------------------------------------------------------------------
__global__ void linear_kernel(const float* __restrict__ x,
                              const float* __restrict__ W,
                              const float* __restrict__ bias) {
    const int BM = 64, BN = 64, BK = 16;
    __shared__ float Xs[BK][BM + 4];
    __shared__ float Ws[BK][BN + 4];

    const int m0 = blockIdx.y * BM;
    const int n0 = blockIdx.x * BN;
    const int tid = threadIdx.x;
    const int tx = tid & 15;
    const int ty = tid >> 4;

    float acc[4][4] = {};

    const int lr = tid >> 2;
    const int lc = (tid & 3) * 4;

    for (int kt = 0; kt < IN_DIM; kt += BK) {
        float4 v = *reinterpret_cast<const float4*>(x + (size_t)(m0 + lr) * IN_DIM + kt + lc);
        Xs[lc + 0][lr] = v.x; Xs[lc + 1][lr] = v.y;
        Xs[lc + 2][lr] = v.z; Xs[lc + 3][lr] = v.w;
        float4 w = *reinterpret_cast<const float4*>(W + (size_t)(n0 + lr) * IN_DIM + kt + lc);
        Ws[lc + 0][lr] = w.x; Ws[lc + 1][lr] = w.y;
        Ws[lc + 2][lr] = w.z; Ws[lc + 3][lr] = w.w;
        __syncthreads();

        #pragma unroll
        for (int k = 0; k < BK; k++) {
            float af[4], bf[4];
            #pragma unroll
            for (int i = 0; i < 4; i++) af[i] = Xs[k][ty * 4 + i];
            #pragma unroll
            for (int j = 0; j < 4; j++) bf[j] = Ws[k][tx * 4 + j];
            #pragma unroll
            for (int i = 0; i < 4; i++)
                #pragma unroll
                for (int j = 0; j < 4; j++)
                    acc[i][j] = fmaf(af[i], bf[j], acc[i][j]);
        }
        __syncthreads();
    }

    float dv[4];
    #pragma unroll
    for (int i = 0; i < 4; i++) dv[i] = g_dinv[m0 + ty * 4 + i];

    // m-major fp32 rows
    #pragma unroll
    for (int i = 0; i < 4; i++) {
        const int gm = m0 + ty * 4 + i;
        float4 o;
        o.x = dv[i] * (acc[i][0] + bias[n0 + tx * 4 + 0]);
        o.y = dv[i] * (acc[i][1] + bias[n0 + tx * 4 + 1]);
        o.z = dv[i] * (acc[i][2] + bias[n0 + tx * 4 + 2]);
        o.w = dv[i] * (acc[i][3] + bias[n0 + tx * 4 + 3]);
        *reinterpret_cast<float4*>(g_feat + (size_t)gm * OUT_DIM + n0 + tx * 4) = o;
    }
    // n-major fp16 rows (4 consecutive k = node index)
    #pragma unroll
    for (int j = 0; j < 4; j++) {
        const int gn = n0 + tx * 4 + j;
        float f[4];
        #pragma unroll
        for (int i = 0; i < 4; i++)
            f[i] = dv[i] * (acc[i][j] + bias[gn]);
        __half2 h0 = __floats2half2_rn(f[0], f[1]);
        __half2 h1 = __floats2half2_rn(f[2], f[3]);
        *reinterpret_cast<uint2*>(g_g16T + (size_t)gn * N_NODES + m0 + ty * 4) =
            make_uint2(h2_bits(h0), h2_bits(h1));
    }
}

// ---------------------------------------------------------------------------
// Kernel 3: out[m,:] = d[m]*( A[m,:] @ g + g[m,:] )  via mma.m16n8k16 fp16.
// CTA 128(M) x 256(N full width), BK=32, 512 threads = 16 warps (4x4),
// warp tile 32x64. Natural-b16 ldmatrix.x4 fragments. 4-stage cp.async ring,
// prefetch distance 3, wait_group 2, ONE sync per chunk.
// Row stride 80 B (16B-aligned, conflict-free LDSM phases: banks r*20 mod 32).
// ---------------------------------------------------------------------------
#define NCH     (N_NODES / 32)        // 512 chunks of k=32
#define RSB     80                    // row stride bytes (32 fp16 data + 16 pad)
#define A_BYTES (128 * RSB)           // 10240
#define B_BYTES (256 * RSB)           // 20480
#define STG_B   (A_BYTES + B_BYTES)   // 30720
#define NSTG    4
#define AGG_SMEM (NSTG * STG_B)       // 122880

__global__ void __launch_bounds__(512, 1)
agg_kernel(float* __restrict__ out) {
    extern __shared__ char smc[];
    const int tid  = threadIdx.x;
    const int wid  = tid >> 5;
    const int lane = tid & 31;
    const int gid  = lane >> 2;     // 0..7
    const int tig  = lane & 3;      // 0..3
    const int q    = lane >> 3;     // ldmatrix quad 0..3
    const int w8   = lane & 7;      // row within quad
    const int wm   = wid & 3;       // warp row  (M blocks of 32)
    const int wn   = wid >> 2;      // warp col  (N blocks of 64)
    const int m0   = blockIdx.x * 128;

    // ---- cp.async geometry (chunk c => byte offset c*64 in each 32KB row) ----
    const int arow = tid >> 2;
    const int aoff = (tid & 3) * 16;                 // 1 x 16B per thread (A: 8 KB)
    const char* agp = reinterpret_cast<const char*>(g_A16 + (size_t)(m0 + arow) * N_NODES) + aoff;
    const int brow = tid >> 1;
    const int boff = (tid & 1) * 32;                 // 2 x 16B per thread (B: 16 KB)
    const char* bgp = reinterpret_cast<const char*>(g_g16T + (size_t)brow * N_NODES) + boff;

    const unsigned sm0 = smem_u32(smc);
    const unsigned sA0 = sm0 + arow * RSB + aoff;
    const unsigned sB0 = sm0 + A_BYTES + brow * RSB + boff;

    // ---- ldmatrix per-lane base addresses (stage 0, ks 0) ----
    // A frag m16n8k16: matrices a0..a3 <- (rowblk=q&1, k-half=q>>1)
    unsigned aL0[2];
    #pragma unroll
    for (int mt = 0; mt < 2; mt++)
        aL0[mt] = sm0 + (wm * 32 + mt * 16 + (q & 1) * 8 + w8) * RSB + (q >> 1) * 16;
    // B frag: x4 covers two n-tiles: (n-rowblk=q>>1, k-half=q&1)
    unsigned bL0[4];
    #pragma unroll
    for (int j = 0; j < 4; j++)
        bL0[j] = sm0 + A_BYTES + (wn * 64 + j * 16 + (q >> 1) * 8 + w8) * RSB + (q & 1) * 16;

    // ---- prologue: prefetch chunks 0,1,2 into stages 0,1,2 ----
    #pragma unroll
    for (int p = 0; p < 3; p++) {
        CP_ASYNC16(sA0 + p * STG_B, agp + (size_t)p * 64);
        #pragma unroll
        for (int i = 0; i < 2; i++)
            CP_ASYNC16(sB0 + p * STG_B + i * 16, bgp + (size_t)p * 64 + i * 16);
        CP_COMMIT();
    }

    float d[2][8][4] = {};

    for (int c = 0; c < NCH; c++) {
        CP_WAIT2();                  // chunk c resident (<=2 groups pending)
        __syncthreads();             // also protects WAR on stage (c+3)&3 (= (c-1)&3)

        // ---- prefetch chunk c+3 into stage (c+3)&3 before compute ----
        const int cp = c + 3;
        if (cp < NCH) {
            const int sp = cp & 3;
            CP_ASYNC16(sA0 + sp * STG_B, agp + (size_t)cp * 64);
            #pragma unroll
            for (int i = 0; i < 2; i++)
                CP_ASYNC16(sB0 + sp * STG_B + i * 16, bgp + (size_t)cp * 64 + i * 16);
        }
        CP_COMMIT();                 // empty group in tail keeps wait_group 2 exact

        // ---- MMA phase on stage c&3 ----
        const unsigned soff = (unsigned)(c & 3) * STG_B;

        #pragma unroll
        for (int ks = 0; ks < 2; ks++) {           // 2 x k16 per 32-chunk
            const unsigned ko = (unsigned)ks * 32; // 16 fp16 = 32 B
            unsigned a[2][4];
            #pragma unroll
            for (int mt = 0; mt < 2; mt++)
                LDSM_X4(a[mt][0], a[mt][1], a[mt][2], a[mt][3], aL0[mt] + soff + ko);
            unsigned bb[4][4];
            #pragma unroll
            for (int j = 0; j < 4; j++)
                LDSM_X4(bb[j][0], bb[j][1], bb[j][2], bb[j][3], bL0[j] + soff + ko);

            #pragma unroll
            for (int j = 0; j < 4; j++) {
                #pragma unroll
                for (int mt = 0; mt < 2; mt++) {
                    mma_f16(d[mt][2*j][0], d[mt][2*j][1], d[mt][2*j][2], d[mt][2*j][3],
                            a[mt][0], a[mt][1], a[mt][2], a[mt][3], bb[j][0], bb[j][1]);
                    mma_f16(d[mt][2*j+1][0], d[mt][2*j+1][1], d[mt][2*j+1][2], d[mt][2*j+1][3],
                            a[mt][0], a[mt][1], a[mt][2], a[mt][3], bb[j][2], bb[j][3]);
                }
            }
        }
    }

    // ---- epilogue: out[m,n] = d[m]*(acc + g[m,n]) ----
    #pragma unroll
    for (int mt = 0; mt < 2; mt++) {
        const int mA = m0 + wm * 32 + mt * 16 + gid;   // rows mA and mA+8
        const float dm0 = g_dinv[mA];
        const float dm1 = g_dinv[mA + 8];
        const float* gf0 = g_feat + (size_t)mA * OUT_DIM;
        const float* gf1 = gf0 + (size_t)8 * OUT_DIM;
        float* op0 = out + (size_t)mA * OUT_DIM;
        float* op1 = op0 + (size_t)8 * OUT_DIM;
        #pragma unroll
        for (int nt = 0; nt < 8; nt++) {
            const int n = wn * 64 + nt * 8 + 2 * tig;
            float2 gv0 = *reinterpret_cast<const float2*>(gf0 + n);
            float2 gv1 = *reinterpret_cast<const float2*>(gf1 + n);
            float2 o0, o1;
            o0.x = dm0 * (d[mt][nt][0] + gv0.x);
            o0.y = dm0 * (d[mt][nt][1] + gv0.y);
            o1.x = dm1 * (d[mt][nt][2] + gv1.x);
            o1.y = dm1 * (d[mt][nt][3] + gv1.y);
            *reinterpret_cast<float2*>(op0 + n) = o0;
            *reinterpret_cast<float2*>(op1 + n) = o1;
        }
    }
}

// ---------------------------------------------------------------------------
extern "C" void kernel_launch(void* const* d_in, const int* in_sizes, int n_in,
                              void* d_out, int out_size) {
    const float* x = (const float*)d_in[0];   // [16384, 512]
    const float* A = (const float*)d_in[1];   // [16384, 16384]
    const float* W = (const float*)d_in[2];   // [256, 512]
    const float* b = (const float*)d_in[3];   // [256]
    float* out = (float*)d_out;               // [16384, 256]

    cudaFuncSetAttribute(agg_kernel, cudaFuncAttributeMaxDynamicSharedMemorySize, AGG_SMEM);

    rowsum_kernel<<<N_NODES, 256>>>(A);
    linear_kernel<<<dim3(OUT_DIM / 64, N_NODES / 64), 256>>>(x, W, b);
    agg_kernel<<<N_NODES / 128, 512, AGG_SMEM>>>(out);
}